// round 14
// baseline (speedup 1.0000x reference)
#include <cuda_runtime.h>

#define NV 8192
#define NC 4096
#define NB 512
#define NE 24576
#define NITER 5
#define EPSF 1e-12f
// clip = float(1 - 1e-7) = 1 - 2^-23.  Image of [-clip, clip] under (1+x)/(1-x):
#define RMAXF 16777215.0f      // = 2^24 - 1
#define RMINF 5.9604648e-8f    // = 1/(2^24 - 1) rounded

#define TPB 1024               // threads per CTA; one CTA = TWO batch elements (float2)
#define VPT (NV / TPB)         // 8 vars / thread
#define CPT (NC / TPB)         // 4 checks / thread
// smem: st planes float2[3][NV] (192KB) + P float2[NC] (32KB) = 229376 B (opt-in)
#define SMEM_BYTES ((3 * NV + NC) * 8)

// Graph structure + caches (device globals: allocation-free per harness rules)
__device__ int      g_inv[NE];           // check -> 6 original edge ids (atomic build order)
__device__ int      g_cnt[NC];           // build counters
__device__ uint4    g_inv8[NC];          // 6 u16 slotted-st offsets per check (bank-scheduled)
__device__ uint2    g_chk4[NV];          // 3 u16 check ids per var, plane order (bank-scheduled)
__device__ unsigned g_eoff[NE];          // original edge id -> slotted st offset (plane*NV + v)
__device__ float2   g_ELp[(NB / 2) * NV]; // exp(llr) pairs per CTA slice (16 MB)

// ---------------------------------------------------------------- var-side plane scheduling
// One warp per 32-var group; all lanes redundantly simulate the greedy via shfl
// broadcasts (counters in registers, 8-bit fields in two u64) — no smem, no sync.
// Also zeroes g_cnt (grid covers NV >= NC threads).
__global__ void var_assign(const int* __restrict__ chk) {
    int t    = blockIdx.x * blockDim.x + threadIdx.x;
    if (t < NC) g_cnt[t] = 0;
    int gwarp = t >> 5, lane = t & 31;
    if (gwarp >= NV / 32) return;
    int v = gwarp * 32 + lane;

    int c0 = chk[3 * v + 0];
    int c1 = chk[3 * v + 1];
    int c2 = chk[3 * v + 2];
    unsigned used = 0;
    int pick[3];

#pragma unroll
    for (int k = 0; k < 3; k++) {
        unsigned long long clo = 0, chi = 0;   // 16 bank-pair counters, 8-bit fields
        for (int i = 0; i < 32; i++) {
            int a0 = __shfl_sync(0xffffffffu, c0, i);
            int a1 = __shfl_sync(0xffffffffu, c1, i);
            int a2 = __shfl_sync(0xffffffffu, c2, i);
            unsigned u = __shfl_sync(0xffffffffu, used, i);
            int best = -1, bc = 1 << 30, bb = 0;
#define VTRY(j, aj)                                                            \
            if (!((u >> j) & 1u)) {                                            \
                int b  = (aj) & 15;                                            \
                int cc = (int)(((b < 8 ? clo : chi) >> ((b & 7) * 8)) & 0xFF); \
                if (cc < bc) { bc = cc; best = j; bb = b; }                    \
            }
            VTRY(0, a0) VTRY(1, a1) VTRY(2, a2)
#undef VTRY
            if (lane == i) { used |= 1u << best; pick[k] = best; }
            if (bb < 8) clo += 1ull << (bb * 8); else chi += 1ull << ((bb - 8) * 8);
        }
    }
    int cs[3] = {c0, c1, c2};
    uint2 w;
    w.x = (unsigned)cs[pick[0]] | ((unsigned)cs[pick[1]] << 16);
    w.y = (unsigned)cs[pick[2]];
    g_chk4[v] = w;
#pragma unroll
    for (int k = 0; k < 3; k++)
        g_eoff[3 * v + pick[k]] = (unsigned)(k * NV + v);
}

// ---------------------------------------------------------------- inverse map (check -> edges)
__global__ void build_inv(const int* __restrict__ chk) {
    int e = blockIdx.x * blockDim.x + threadIdx.x;
    if (e < NE) {
        int c = chk[e];
        int s = atomicAdd(&g_cnt[c], 1);
        g_inv[c * 6 + s] = e;
    }
}

// ---------------------------------------------------------------- check-side slot scheduling
// One warp per 32-check group, shfl-redundant greedy (same schedule as smem version).
__global__ void check_pack() {
    int t    = blockIdx.x * blockDim.x + threadIdx.x;
    int gwarp = t >> 5, lane = t & 31;
    if (gwarp >= NC / 32) return;
    int ch = gwarp * 32 + lane;

    int a[6];
#pragma unroll
    for (int k = 0; k < 6; k++) a[k] = g_inv[ch * 6 + k];
    // ascending edge-id sort: deterministic base product order (matches segment ops)
#pragma unroll
    for (int x = 1; x < 6; x++)
#pragma unroll
        for (int j = x; j > 0; j--)
            if (a[j] < a[j - 1]) { int s = a[j]; a[j] = a[j - 1]; a[j - 1] = s; }

    unsigned o0 = g_eoff[a[0]], o1 = g_eoff[a[1]], o2 = g_eoff[a[2]];
    unsigned o3 = g_eoff[a[3]], o4 = g_eoff[a[4]], o5 = g_eoff[a[5]];
    unsigned used = 0;
    unsigned slot[6];

#pragma unroll
    for (int k = 0; k < 6; k++) {
        unsigned long long clo = 0, chi = 0;
        for (int i = 0; i < 32; i++) {
            unsigned q0 = __shfl_sync(0xffffffffu, o0, i);
            unsigned q1 = __shfl_sync(0xffffffffu, o1, i);
            unsigned q2 = __shfl_sync(0xffffffffu, o2, i);
            unsigned q3 = __shfl_sync(0xffffffffu, o3, i);
            unsigned q4 = __shfl_sync(0xffffffffu, o4, i);
            unsigned q5 = __shfl_sync(0xffffffffu, o5, i);
            unsigned u  = __shfl_sync(0xffffffffu, used, i);
            int best = -1, bc = 1 << 30, bb = 0; unsigned bo = 0;
#define CTRY(j, qj)                                                            \
            if (!((u >> j) & 1u)) {                                            \
                int b  = (int)((qj) & 15u);                                    \
                int cc = (int)(((b < 8 ? clo : chi) >> ((b & 7) * 8)) & 0xFF); \
                if (cc < bc) { bc = cc; best = j; bo = qj; bb = b; }           \
            }
            CTRY(0, q0) CTRY(1, q1) CTRY(2, q2) CTRY(3, q3) CTRY(4, q4) CTRY(5, q5)
#undef CTRY
            if (lane == i) { used |= 1u << best; slot[k] = bo; }
            if (bb < 8) clo += 1ull << (bb * 8); else chi += 1ull << ((bb - 8) * 8);
        }
    }
    uint4 w;
    w.x = slot[0] | (slot[1] << 16);
    w.y = slot[2] | (slot[3] << 16);
    w.z = slot[4] | (slot[5] << 16);
    w.w = 0;
    g_inv8[ch] = w;
}

// ---------------------------------------------------------------- helpers
__device__ __forceinline__ float tanh_half_from_exp(float el) {
    float t = __fdividef(el - 1.0f, el + 1.0f);
    return t + copysignf(EPSF, t);
}

// r = (st+P)/(st-P) kept as a (n,d) pair — clamp replicates the reference clip,
// exponent-trick normalization keeps later triple-products in normal fp32 range.
__device__ __forceinline__ void nd_edge(float st, float p, float& n, float& d) {
    n = st + p; d = st - p;
    float an = fabsf(n), ad = fabsf(d);
    if (an > RMAXF * ad)      { n = RMAXF; d = 1.0f; }
    else if (an < RMINF * ad) { n = RMINF; d = 1.0f; }
    else {
        unsigned ex = (__float_as_uint(d) >> 23) & 0xFFu;
        float s = __uint_as_float((254u - ex) << 23);   // 2^(127-ex):  |d*s| in [1,2)
        n *= s; d *= s;
    }
}

// st' = tanh(msg/2)+eps from u = EL*r_a*r_b given pair products: one RCP total.
__device__ __forceinline__ float st_next(float EL, float nn, float dd) {
    float A = EL * nn;
    float t = __fdividef(A - dd, A + dd);
    return t + copysignf(EPSF, t);
}

// ---------------------------------------------------------------- persistent per-batch-pair decoder
__global__ void __launch_bounds__(TPB, 1)
spa_kernel(const float* __restrict__ llr, float* __restrict__ out) {
    extern __shared__ float2 sm[];
    float2* s_st = sm;            // 3*NV float2 (plane-slotted: var v at {v, NV+v, 2NV+v})
    float2* s_P  = sm + 3 * NV;   // NC float2

    int tid = threadIdx.x;
    int b0  = 2 * blockIdx.x;
    const float* llr0 = llr + (b0 + 0) * NV;
    const float* llr1 = llr + (b0 + 1) * NV;
    float2* ELrow = g_ELp + blockIdx.x * NV;

    // init: EL = exp(llr) cached to global slice; iter-0 st on all 3 planes
#pragma unroll
    for (int m = 0; m < VPT; m++) {
        int v = tid + m * TPB;
        float2 E;
        E.x = __expf(llr0[v]);
        E.y = __expf(llr1[v]);
        ELrow[v] = E;
        float2 t;
        t.x = tanh_half_from_exp(E.x);
        t.y = tanh_half_from_exp(E.y);
        s_st[v]          = t;
        s_st[NV + v]     = t;
        s_st[2 * NV + v] = t;
    }
    __syncthreads();

    for (int it = 0; it < NITER; it++) {
        // ---- check phase: P[c] = signed product of 6 st (bank-scheduled slot order)
#pragma unroll
        for (int m = 0; m < CPT; m++) {
            int c = tid + m * TPB;
            uint4 w = g_inv8[c];
            float2 a0 = s_st[w.x & 0xFFFF];
            float2 a1 = s_st[w.x >> 16];
            float2 a2 = s_st[w.y & 0xFFFF];
            float2 a3 = s_st[w.y >> 16];
            float2 a4 = s_st[w.z & 0xFFFF];
            float2 a5 = s_st[w.z >> 16];
            float2 p;
            p.x = ((((a0.x * a1.x) * a2.x) * a3.x) * a4.x) * a5.x;
            p.y = ((((a0.y * a1.y) * a2.y) * a3.y) * a4.y) * a5.y;
            s_P[c] = p;
        }
        __syncthreads();

        // ---- var phase: out(it) + next-iteration st via (n,d) pair algebra
        int ob0 = it * (NB * NV) + (b0 + 0) * NV;
        int ob1 = it * (NB * NV) + (b0 + 1) * NV;
#pragma unroll
        for (int m = 0; m < VPT; m++) {
            int v = tid + m * TPB;
            float2 st0 = s_st[v];
            float2 st1 = s_st[NV + v];
            float2 st2 = s_st[2 * NV + v];
            uint2 cw = g_chk4[v];
            float2 p0 = s_P[cw.x & 0xFFFF];
            float2 p1 = s_P[cw.x >> 16];
            float2 p2 = s_P[cw.y];
            float2 E = ELrow[v];

            float n0x, d0x, n1x, d1x, n2x, d2x;
            float n0y, d0y, n1y, d1y, n2y, d2y;
            nd_edge(st0.x, p0.x, n0x, d0x);
            nd_edge(st1.x, p1.x, n1x, d1x);
            nd_edge(st2.x, p2.x, n2x, d2x);
            nd_edge(st0.y, p0.y, n0y, d0y);
            nd_edge(st1.y, p1.y, n1y, d1y);
            nd_edge(st2.y, p2.y, n2y, d2y);

            // pairwise products (shared between out and st updates)
            float n01x = n0x * n1x, n12x = n1x * n2x, n02x = n0x * n2x;
            float d01x = d0x * d1x, d12x = d1x * d2x, d02x = d0x * d2x;
            float n01y = n0y * n1y, n12y = n1y * n2y, n02y = n0y * n2y;
            float d01y = d0y * d1y, d12y = d1y * d2y, d02y = d0y * d2y;

            // out = llr + sum ext = log(EL * r0*r1*r2)
            float Tx = __fdividef(n01x * n2x, d01x * d2x);
            float Ty = __fdividef(n01y * n2y, d01y * d2y);
            out[ob0 + v] = __logf(E.x * Tx);
            out[ob1 + v] = __logf(E.y * Ty);

            if (it < NITER - 1) {
                float2 w0, w1, w2;
                w0.x = st_next(E.x, n12x, d12x);
                w0.y = st_next(E.y, n12y, d12y);
                w1.x = st_next(E.x, n02x, d02x);
                w1.y = st_next(E.y, n02y, d02y);
                w2.x = st_next(E.x, n01x, d01x);
                w2.y = st_next(E.y, n01y, d01y);
                s_st[v]          = w0;
                s_st[NV + v]     = w1;
                s_st[2 * NV + v] = w2;
            }
        }
        __syncthreads();
    }
}

// ---------------------------------------------------------------- launch
extern "C" void kernel_launch(void* const* d_in, const int* in_sizes, int n_in,
                              void* d_out, int out_size) {
    const float* llr = (const float*)d_in[0];
    // d_in[1] = var_index: structured as repeat(arange(NV), 3) -> not needed
    const int* chk = (const int*)d_in[2];
    float* out = (float*)d_out;

    cudaFuncSetAttribute(spa_kernel, cudaFuncAttributeMaxDynamicSharedMemorySize,
                         SMEM_BYTES);

    var_assign<<<NV / 256, 256>>>(chk);          // also zeroes g_cnt
    build_inv<<<(NE + 255) / 256, 256>>>(chk);
    check_pack<<<NC / 256, 256>>>();
    spa_kernel<<<NB / 2, TPB, SMEM_BYTES>>>(llr, out);
}

// round 15
// speedup vs baseline: 1.5833x; 1.5833x over previous
#include <cuda_runtime.h>

#define NV 8192
#define NC 4096
#define NB 512
#define NE 24576
#define NITER 5
#define EPSF 1e-12f
// clip = float(1 - 1e-7) = 1 - 2^-23.  Image of [-clip, clip] under (1+x)/(1-x):
#define RMAXF 16777215.0f      // = 2^24 - 1
#define RMINF 5.9604648e-8f    // = 1/(2^24 - 1) rounded

#define TPB 1024               // threads per CTA; one CTA = TWO batch elements (float2)
#define VPT (NV / TPB)         // 8 vars / thread
#define CPT (NC / TPB)         // 4 checks / thread
// smem: st planes float2[3][NV] (192KB) + P float2[NC] (32KB) = 229376 B (opt-in)
#define SMEM_BYTES ((3 * NV + NC) * 8)

// Graph structure + caches (device globals: allocation-free per harness rules)
__device__ int    g_inv[NE];             // check -> 6 edge ids (atomic build order)
__device__ int    g_cnt[NC];             // build counters
__device__ uint4  g_inv8[NC];            // 6 u16 slotted-st offsets per check (edge-ascending)
__device__ uint2  g_chk4[NV];            // 3 u16 check ids per var
__device__ float2 g_Ep[(NB / 2) * NV];   // exp(llr) pairs per CTA slice (16 MB)

// ---------------------------------------------------------------- index build
__global__ void zero_cnt() {
    int i = blockIdx.x * blockDim.x + threadIdx.x;
    if (i < NC) g_cnt[i] = 0;
}

__global__ void build_inv(const int* __restrict__ chk) {
    int e = blockIdx.x * blockDim.x + threadIdx.x;
    if (e < NE) {
        int c = chk[e];
        int s = atomicAdd(&g_cnt[c], 1);
        g_inv[c * 6 + s] = e;
    }
}

// Sort each check's 6 edges ascending (deterministic product order matching the
// reference's segment ops), map edge id -> plane-slotted st offset
// off(e) = (e%3)*NV + e/3, pack to u16. Also pack per-var check ids.
__global__ void pack_idx(const int* __restrict__ chk) {
    int i = blockIdx.x * blockDim.x + threadIdx.x;
    if (i < NC) {
        int a[6];
#pragma unroll
        for (int k = 0; k < 6; k++) a[k] = g_inv[i * 6 + k];
#pragma unroll
        for (int x = 1; x < 6; x++)
#pragma unroll
            for (int j = x; j > 0; j--)
                if (a[j] < a[j - 1]) { int t = a[j]; a[j] = a[j - 1]; a[j - 1] = t; }
        unsigned o[6];
#pragma unroll
        for (int k = 0; k < 6; k++) {
            int e = a[k];
            o[k] = (unsigned)((e % 3) * NV + (e / 3));
        }
        uint4 w;
        w.x = o[0] | (o[1] << 16);
        w.y = o[2] | (o[3] << 16);
        w.z = o[4] | (o[5] << 16);
        w.w = 0;
        g_inv8[i] = w;
    }
    if (i < NV) {
        uint2 w;
        w.x = (unsigned)chk[3 * i] | ((unsigned)chk[3 * i + 1] << 16);
        w.y = (unsigned)chk[3 * i + 2];
        g_chk4[i] = w;
    }
}

// ---------------------------------------------------------------- helpers
__device__ __forceinline__ float tanh_half_from_exp(float el) {
    float t = __fdividef(el - 1.0f, el + 1.0f);
    return t + copysignf(EPSF, t);
}

__device__ __forceinline__ float clamp_r(float r) {
    return fminf(fmaxf(r, RMINF), RMAXF);
}

__device__ __forceinline__ float2 r_pair(float2 st, float2 p) {
    float2 r;
    r.x = clamp_r(__fdividef(st.x + p.x, st.x - p.x));
    r.y = clamp_r(__fdividef(st.y + p.y, st.y - p.y));
    return r;
}

// ---------------------------------------------------------------- persistent per-batch-pair decoder
// One CTA decodes TWO batch elements entirely in shared memory (float2 lanes):
//   s_st[3*NV] : plane-slotted st — var v's edges at {v, NV+v, 2NV+v}
//   s_P[NC]    : per-check signed product of 6 st
// exp(llr) pairs cached in a global slice at init -> var phase has zero EX2 and
// no llr loads (out = log(EL * r0*r1*r2)).
__global__ void __launch_bounds__(TPB, 1)
spa_kernel(const float* __restrict__ llr, float* __restrict__ out) {
    extern __shared__ float2 sm[];
    float2* s_st = sm;            // 3*NV float2
    float2* s_P  = sm + 3 * NV;   // NC float2

    int tid = threadIdx.x;
    int b0  = 2 * blockIdx.x;
    const float* llr0 = llr + (b0 + 0) * NV;
    const float* llr1 = llr + (b0 + 1) * NV;
    float2* Erow = g_Ep + blockIdx.x * NV;

    // init: EL = exp(llr) cached; iter-0 messages msg = llr on all 3 planes
#pragma unroll
    for (int m = 0; m < VPT; m++) {
        int v = tid + m * TPB;
        float2 E;
        E.x = __expf(llr0[v]);
        E.y = __expf(llr1[v]);
        Erow[v] = E;
        float2 t;
        t.x = tanh_half_from_exp(E.x);
        t.y = tanh_half_from_exp(E.y);
        s_st[v]          = t;
        s_st[NV + v]     = t;
        s_st[2 * NV + v] = t;
    }
    __syncthreads();

    for (int it = 0; it < NITER; it++) {
        // ---- check phase: P[c] = signed product of 6 st (ascending edge order)
#pragma unroll
        for (int m = 0; m < CPT; m++) {
            int c = tid + m * TPB;
            uint4 w = g_inv8[c];
            float2 a0 = s_st[w.x & 0xFFFF];
            float2 a1 = s_st[w.x >> 16];
            float2 a2 = s_st[w.y & 0xFFFF];
            float2 a3 = s_st[w.y >> 16];
            float2 a4 = s_st[w.z & 0xFFFF];
            float2 a5 = s_st[w.z >> 16];
            float2 p;
            p.x = ((((a0.x * a1.x) * a2.x) * a3.x) * a4.x) * a5.x;
            p.y = ((((a0.y * a1.y) * a2.y) * a3.y) * a4.y) * a5.y;
            s_P[c] = p;
        }
        __syncthreads();

        // ---- var phase: out(it) + next-iteration st
        int ob0 = it * (NB * NV) + (b0 + 0) * NV;
        int ob1 = it * (NB * NV) + (b0 + 1) * NV;
#pragma unroll
        for (int m = 0; m < VPT; m++) {
            int v = tid + m * TPB;
            float2 st0 = s_st[v];
            float2 st1 = s_st[NV + v];
            float2 st2 = s_st[2 * NV + v];
            uint2 cw = g_chk4[v];
            float2 p0 = s_P[cw.x & 0xFFFF];
            float2 p1 = s_P[cw.x >> 16];
            float2 p2 = s_P[cw.y];

            // r_e = e^{ext_e} = (st+P)/(st-P); signs cancel, r >= 0;
            // clamp is the exact image of the reference's loo clip.
            float2 r0 = r_pair(st0, p0);
            float2 r1 = r_pair(st1, p1);
            float2 r2 = r_pair(st2, p2);

            float2 E = Erow[v];
            float r12x = r1.x * r2.x;
            float r12y = r1.y * r2.y;
            // out = llr + sum of ext = log(EL * r0*r1*r2)
            out[ob0 + v] = __logf(E.x * (r0.x * r12x));
            out[ob1 + v] = __logf(E.y * (r0.y * r12y));

            if (it < NITER - 1) {
                // e^{msg_e} = e^llr * product of the OTHER two r's
                float2 w0, w1, w2;
                w0.x = tanh_half_from_exp(E.x * r12x);
                w0.y = tanh_half_from_exp(E.y * r12y);
                w1.x = tanh_half_from_exp(E.x * (r0.x * r2.x));
                w1.y = tanh_half_from_exp(E.y * (r0.y * r2.y));
                w2.x = tanh_half_from_exp(E.x * (r0.x * r1.x));
                w2.y = tanh_half_from_exp(E.y * (r0.y * r1.y));
                s_st[v]          = w0;
                s_st[NV + v]     = w1;
                s_st[2 * NV + v] = w2;
            }
        }
        if (it < NITER - 1) __syncthreads();
    }
}

// ---------------------------------------------------------------- launch
extern "C" void kernel_launch(void* const* d_in, const int* in_sizes, int n_in,
                              void* d_out, int out_size) {
    const float* llr = (const float*)d_in[0];
    // d_in[1] = var_index: structured as repeat(arange(NV), 3) -> not needed
    const int* chk = (const int*)d_in[2];
    float* out = (float*)d_out;

    cudaFuncSetAttribute(spa_kernel, cudaFuncAttributeMaxDynamicSharedMemorySize,
                         SMEM_BYTES);

    zero_cnt<<<(NC + 255) / 256, 256>>>();
    build_inv<<<(NE + 255) / 256, 256>>>(chk);
    pack_idx<<<(NV + 255) / 256, 256>>>(chk);
    spa_kernel<<<NB / 2, TPB, SMEM_BYTES>>>(llr, out);
}